// round 7
// baseline (speedup 1.0000x reference)
#include <cuda_runtime.h>
#include <cuda_fp16.h>
#include <cstdint>
#include <stdint.h>
#include <math.h>

#define B_  32
#define D_  256
#define K_  1024
#define HW_ 1024
#define N_  32768
#define Q_ELEMS 8388608
#define ENC_OFF 8388610
#define MARGIN 2.5e-4f

// SMEM layout (bytes): A_hi [128][260]h, A_lo [128][260]h, B 2 bufs x 8192B, cnorm 4KB
#define SM_AHI   0
#define SM_ALO   66560
#define SM_B     133120
#define SM_CN    149504
#define SMEM_TOTAL 153600

// -------- scratch --------
__device__ __half g_bimg[524288];  // [8 nc][16 ds][2 hi/lo][128 n][16 k]
__device__ float g_cnorm[K_];
__device__ float g_znorm[N_];
__device__ int   g_idx[N_];
__device__ int   g_counts[K_];
__device__ float g_part[8192];
__device__ int   g_nflag;
__device__ int   g_flag[N_];

#define MMA16816(d, a, b) \
    asm volatile("mma.sync.aligned.m16n8k16.row.col.f32.f16.f16.f32 " \
        "{%0,%1,%2,%3}, {%4,%5,%6,%7}, {%8,%9}, {%0,%1,%2,%3};" \
        : "+f"((d)[0]), "+f"((d)[1]), "+f"((d)[2]), "+f"((d)[3]) \
        : "r"((a)[0]), "r"((a)[1]), "r"((a)[2]), "r"((a)[3]), \
          "r"((b)[0]), "r"((b)[1]))

// -------- cnorm + zero counts + zero flag counter --------
__global__ void cnorm_kernel(const float* __restrict__ cb) {
    int tid = threadIdx.x;
    int gtid = blockIdx.x * 256 + tid;
    if (gtid < K_) g_counts[gtid] = 0;
    if (gtid == 0) g_nflag = 0;
    int wid = tid >> 5, lane = tid & 31;
    int code = blockIdx.x * 8 + wid;
    float s = 0.f;
    #pragma unroll
    for (int j = 0; j < 8; j++) {
        float v = cb[(size_t)code * D_ + lane + 32 * j];
        s = fmaf(v, v, s);
    }
    #pragma unroll
    for (int o = 16; o > 0; o >>= 1) s += __shfl_down_sync(0xffffffffu, s, o);
    if (lane == 0) g_cnorm[code] = s;
}

// -------- znorm (identical arithmetic to the R2 kernel that matched reference) --------
__global__ void znorm_kernel(const float* __restrict__ z_e) {
    int r = blockIdx.x * 256 + threadIdx.x;
    int b = r >> 10, hw = r & 1023;
    const float* p = z_e + (size_t)b * (D_ * HW_) + hw;
    float s = 0.f;
    #pragma unroll 8
    for (int d = 0; d < D_; d++) {
        float v = p[(size_t)d * HW_];
        s = fmaf(v, v, s);
    }
    g_znorm[r] = s;
}

// -------- codebook -> fp16 hi/lo packed slabs --------
__global__ void prep_b_kernel(const float* __restrict__ cb) {
    int e = blockIdx.x * 256 + threadIdx.x;   // 262144
    int code = e >> 8;
    int d = e & 255;
    float v = cb[(size_t)code * D_ + d];
    __half h = __float2half(v);
    __half l = __float2half(v - __half2float(h));
    int nc = code >> 7, n = code & 127;
    int ds = d >> 4, k = d & 15;
    size_t base = ((size_t)(nc * 16 + ds) * 2) * 2048 + (size_t)n * 16 + k;
    g_bimg[base] = h;            // hi slab
    g_bimg[base + 2048] = l;     // lo slab
}

// -------- main: HMMA distance GEMM (fp16 hi/lo split) + argmin + top-2 gap flag --------
__global__ void __launch_bounds__(256) vq_hmma_kernel(const float* __restrict__ z_e) {
    extern __shared__ char smem[];
    __half* Ah = (__half*)(smem + SM_AHI);     // [128][260]
    __half* Al = (__half*)(smem + SM_ALO);
    __half* Bb = (__half*)(smem + SM_B);       // [2 buf][2 hi/lo][128][16]
    float*  cn = (float*)(smem + SM_CN);

    int tid = threadIdx.x;
    int w = tid >> 5, lane = tid & 31;
    int g = lane >> 2, tg = lane & 3;
    int wM = w & 3, wN = w >> 2;               // 4 M-warps x 2 N-warps
    int R0 = blockIdx.x * 128;
    int b = R0 >> 10, hw0 = R0 & 1023;
    const float* zbase = z_e + (size_t)b * (D_ * HW_) + hw0;

    #pragma unroll
    for (int i = tid; i < K_; i += 256) cn[i] = g_cnorm[i];

    for (int e = tid; e < 32768; e += 256) {
        int d = e >> 7, r = e & 127;
        float z = zbase[(size_t)d * HW_ + r];
        __half h = __float2half(z);
        __half l = __float2half(z - __half2float(h));
        Ah[r * 260 + d] = h;
        Al[r * 260 + d] = l;
    }
    __syncthreads();

    float znr[4];
    #pragma unroll
    for (int i = 0; i < 4; i++) znr[i] = g_znorm[R0 + wM * 32 + 8 * i + g];

    float v1r[4], v2r[4];
    int   k1r[4];
    #pragma unroll
    for (int i = 0; i < 4; i++) { v1r[i] = 3.402823466e38f; v2r[i] = 3.402823466e38f; k1r[i] = 0; }

    const int4* bimg = (const int4*)g_bimg;

    for (int n0 = 0; n0 < 8; n0++) {
        float acc[2][8][4];
        #pragma unroll
        for (int mt = 0; mt < 2; mt++)
            #pragma unroll
            for (int nt = 0; nt < 8; nt++)
                #pragma unroll
                for (int c = 0; c < 4; c++) acc[mt][nt][c] = 0.f;

        const int4* src = bimg + (size_t)(n0 * 16) * 512;
        int4 p0 = src[tid], p1 = src[tid + 256];

        for (int ds = 0; ds < 16; ds++) {
            int buf = ds & 1;
            int4* bd = (int4*)(Bb + buf * 4096);
            bd[tid] = p0; bd[tid + 256] = p1;
            __syncthreads();
            if (ds < 15) {
                const int4* s2 = bimg + (size_t)(n0 * 16 + ds + 1) * 512;
                p0 = s2[tid]; p1 = s2[tid + 256];
            }
            int k0 = ds * 16;
            const __half* Bh = Bb + buf * 4096;
            const __half* Bl = Bh + 2048;

            uint32_t ah[2][4], al[2][4], bh[8][2], bl[8][2];
            #pragma unroll
            for (int mt = 0; mt < 2; mt++) {
                const __half* pa = Ah + (wM * 32 + mt * 16 + g) * 260 + k0 + tg * 2;
                ah[mt][0] = *(const uint32_t*)pa;
                ah[mt][1] = *(const uint32_t*)(pa + 8 * 260);
                ah[mt][2] = *(const uint32_t*)(pa + 8);
                ah[mt][3] = *(const uint32_t*)(pa + 8 * 260 + 8);
            }
            #pragma unroll
            for (int nt = 0; nt < 8; nt++) {
                const __half* pb = Bh + (wN * 64 + nt * 8 + g) * 16 + tg * 2;
                bh[nt][0] = *(const uint32_t*)pb;
                bh[nt][1] = *(const uint32_t*)(pb + 8);
            }
            #pragma unroll
            for (int mt = 0; mt < 2; mt++)
                #pragma unroll
                for (int nt = 0; nt < 8; nt++) MMA16816(acc[mt][nt], ah[mt], bh[nt]);

            #pragma unroll
            for (int mt = 0; mt < 2; mt++) {
                const __half* pa = Al + (wM * 32 + mt * 16 + g) * 260 + k0 + tg * 2;
                al[mt][0] = *(const uint32_t*)pa;
                al[mt][1] = *(const uint32_t*)(pa + 8 * 260);
                al[mt][2] = *(const uint32_t*)(pa + 8);
                al[mt][3] = *(const uint32_t*)(pa + 8 * 260 + 8);
            }
            #pragma unroll
            for (int mt = 0; mt < 2; mt++)
                #pragma unroll
                for (int nt = 0; nt < 8; nt++) MMA16816(acc[mt][nt], al[mt], bh[nt]);

            #pragma unroll
            for (int nt = 0; nt < 8; nt++) {
                const __half* pb = Bl + (wN * 64 + nt * 8 + g) * 16 + tg * 2;
                bl[nt][0] = *(const uint32_t*)pb;
                bl[nt][1] = *(const uint32_t*)(pb + 8);
            }
            #pragma unroll
            for (int mt = 0; mt < 2; mt++)
                #pragma unroll
                for (int nt = 0; nt < 8; nt++) MMA16816(acc[mt][nt], ah[mt], bl[nt]);
        }

        // epilogue: scores + running top-2 (ascending k per thread)
        #pragma unroll
        for (int nt = 0; nt < 8; nt++)
            #pragma unroll
            for (int mt = 0; mt < 2; mt++)
                #pragma unroll
                for (int c = 0; c < 4; c++) {
                    int i = mt * 2 + (c >> 1);
                    int k = n0 * 128 + wN * 64 + nt * 8 + tg * 2 + (c & 1);
                    float A = znr[i] + cn[k];
                    float v = A - 2.0f * acc[mt][nt][c];
                    if (v < v1r[i]) { v2r[i] = v1r[i]; v1r[i] = v; k1r[i] = k; }
                    else if (v < v2r[i]) { v2r[i] = v; }
                }
    }
    __syncthreads();

    // reduce top-2 across the 4 tg lanes, lowest-index tie-break on v1
    float* sv1 = (float*)(Bb);
    int*   sk1 = (int*)(Bb + 2048);
    float* sv2 = (float*)(Bb + 4096);
    #pragma unroll
    for (int i = 0; i < 4; i++) {
        float v1 = v1r[i], v2 = v2r[i]; int k1 = k1r[i];
        #pragma unroll
        for (int o = 1; o <= 2; o <<= 1) {
            float ov1 = __shfl_xor_sync(0xffffffffu, v1, o);
            int   ok1 = __shfl_xor_sync(0xffffffffu, k1, o);
            float ov2 = __shfl_xor_sync(0xffffffffu, v2, o);
            float vmax = fmaxf(v1, ov1);
            v2 = fminf(fminf(v2, ov2), vmax);
            if (ov1 < v1 || (ov1 == v1 && ok1 < k1)) { v1 = ov1; k1 = ok1; }
        }
        if (tg == 0) {
            int row = wM * 32 + 8 * i + g;
            sv1[wN * 128 + row] = v1;
            sk1[wN * 128 + row] = k1;
            sv2[wN * 128 + row] = v2;
        }
    }
    __syncthreads();
    if (tid < 128) {
        float a1 = sv1[tid]; int ak = sk1[tid]; float a2 = sv2[tid];
        float b1 = sv1[128 + tid]; int bk = sk1[128 + tid]; float b2 = sv2[128 + tid];
        float vmax = fmaxf(a1, b1);
        float v2 = fminf(fminf(a2, b2), vmax);
        float v1 = a1; int k1 = ak;
        if (b1 < v1 || (b1 == v1 && bk < k1)) { v1 = b1; k1 = bk; }
        int row = R0 + tid;
        g_idx[row] = k1;
        if (v2 - v1 < MARGIN) {
            int pos = atomicAdd(&g_nflag, 1);
            g_flag[pos] = row;
        }
    }
}

// -------- rescue: exact fp32 rescoring of flagged rows (R2 arithmetic) --------
__global__ void rescore_kernel(const float* __restrict__ z_e,
                               const float* __restrict__ cb) {
    __shared__ float zrow[256];
    __shared__ float rv[256];
    __shared__ int   rk[256];
    int t = threadIdx.x;
    int total = *(volatile int*)&g_nflag;
    for (int i = blockIdx.x; i < total; i += gridDim.x) {
        int row = g_flag[i];
        int b = row >> 10, hw = row & 1023;
        const float* zp = z_e + (size_t)b * (D_ * HW_) + hw;
        zrow[t] = zp[(size_t)t * HW_];
        __syncthreads();
        float zn = g_znorm[row];
        float bv = 3.402823466e38f; int bk = 0;
        #pragma unroll
        for (int j = 0; j < 4; j++) {
            int k = j * 256 + t;                 // ascending k per thread
            const float* cp = cb + (size_t)k * D_;
            float dot = 0.f;
            #pragma unroll 8
            for (int d = 0; d < 256; d++) dot = fmaf(zrow[d], cp[d], dot);
            float A = zn + g_cnorm[k];
            float v = A - 2.0f * dot;
            if (v < bv) { bv = v; bk = k; }
        }
        rv[t] = bv; rk[t] = bk;
        __syncthreads();
        for (int o = 128; o > 0; o >>= 1) {
            if (t < o) {
                float ov = rv[t + o]; int ok = rk[t + o];
                if (ov < rv[t] || (ov == rv[t] && ok < rk[t])) { rv[t] = ov; rk[t] = ok; }
            }
            __syncthreads();
        }
        if (t == 0) g_idx[row] = rk[0];
        __syncthreads();
    }
}

// -------- gather quantized (NCHW) + per-block SSE partials --------
__global__ void output_kernel(const float* __restrict__ z_e,
                              const float* __restrict__ cb,
                              float* __restrict__ out) {
    __shared__ float red[256];
    int tid = threadIdx.x;
    size_t e = ((size_t)blockIdx.x * 256 + tid) * 4;
    int w = (int)(e & 31);
    int h = (int)((e >> 5) & 31);
    int d = (int)((e >> 10) & 255);
    int b = (int)(e >> 18);
    int n = b * 1024 + h * 32 + w;
    float4 z = *reinterpret_cast<const float4*>(z_e + e);
    float q0 = cb[(size_t)g_idx[n + 0] * D_ + d];
    float q1 = cb[(size_t)g_idx[n + 1] * D_ + d];
    float q2 = cb[(size_t)g_idx[n + 2] * D_ + d];
    float q3 = cb[(size_t)g_idx[n + 3] * D_ + d];
    *reinterpret_cast<float4*>(out + e) = make_float4(q0, q1, q2, q3);
    float d0 = q0 - z.x, d1 = q1 - z.y, d2 = q2 - z.z, d3 = q3 - z.w;
    red[tid] = d0 * d0 + d1 * d1 + d2 * d2 + d3 * d3;
    __syncthreads();
    for (int o = 128; o > 0; o >>= 1) {
        if (tid < o) red[tid] += red[tid + o];
        __syncthreads();
    }
    if (tid == 0) g_part[blockIdx.x] = red[0];
}

// -------- zero-fill encodings --------
__global__ void zero_enc_kernel(float* __restrict__ out) {
    float2* enc = reinterpret_cast<float2*>(out + ENC_OFF);
    size_t t = (size_t)blockIdx.x * 256 + threadIdx.x;
    #pragma unroll
    for (int i = 0; i < 8; i++)
        enc[t + (size_t)i * 2097152] = make_float2(0.f, 0.f);
}

// -------- scatter one-hot + counts --------
__global__ void scatter_kernel(float* __restrict__ out) {
    int n = blockIdx.x * 256 + threadIdx.x;
    int idx = g_idx[n];
    atomicAdd(&g_counts[idx], 1);
    out[ENC_OFF + (size_t)n * K_ + idx] = 1.0f;
}

// -------- finalize: loss + perplexity --------
__global__ void finalize_kernel(float* __restrict__ out) {
    __shared__ float red[1024];
    int t = threadIdx.x;
    float s = 0.f;
    #pragma unroll
    for (int i = 0; i < 8; i++) s += g_part[t + i * 1024];
    red[t] = s;
    __syncthreads();
    for (int o = 512; o > 0; o >>= 1) {
        if (t < o) red[t] += red[t + o];
        __syncthreads();
    }
    float sse = red[0];
    __syncthreads();
    float p = (float)g_counts[t] * (1.0f / 32768.0f);
    red[t] = p * logf(p + 1e-10f);
    __syncthreads();
    for (int o = 512; o > 0; o >>= 1) {
        if (t < o) red[t] += red[t + o];
        __syncthreads();
    }
    if (t == 0) {
        float mse = sse * (1.0f / 8388608.0f);
        out[Q_ELEMS]     = 1.25f * mse;
        out[Q_ELEMS + 1] = expf(-red[0]);
    }
}

extern "C" void kernel_launch(void* const* d_in, const int* in_sizes, int n_in,
                              void* d_out, int out_size) {
    const float* z_e = (const float*)d_in[0];
    const float* cb  = (const float*)d_in[1];
    if (n_in >= 2 && in_sizes[0] < in_sizes[1]) {
        z_e = (const float*)d_in[1];
        cb  = (const float*)d_in[0];
    }
    float* out = (float*)d_out;

    cudaFuncSetAttribute(vq_hmma_kernel, cudaFuncAttributeMaxDynamicSharedMemorySize, SMEM_TOTAL);

    cnorm_kernel<<<128, 256>>>(cb);
    znorm_kernel<<<128, 256>>>(z_e);
    prep_b_kernel<<<1024, 256>>>(cb);
    vq_hmma_kernel<<<256, 256, SMEM_TOTAL>>>(z_e);
    rescore_kernel<<<512, 256>>>(z_e, cb);
    output_kernel<<<8192, 256>>>(z_e, cb, out);
    zero_enc_kernel<<<8192, 256>>>(out);
    scatter_kernel<<<128, 256>>>(out);
    finalize_kernel<<<1, 1024>>>(out);
}

// round 10
// speedup vs baseline: 3.9748x; 3.9748x over previous
#include <cuda_runtime.h>
#include <cuda_fp16.h>
#include <cstdint>
#include <stdint.h>
#include <math.h>

#define B_  32
#define D_  256
#define K_  1024
#define HW_ 1024
#define N_  32768
#define Q_ELEMS 8388608
#define ENC_OFF 8388610
#define CAND_T 2.5e-4f

// SMEM layout (bytes): A_hi [128][260]h, A_lo [128][260]h, B 2 bufs x 8192B, cnorm 4KB
#define SM_AHI   0
#define SM_ALO   66560
#define SM_B     133120
#define SM_CN    149504
#define SMEM_TOTAL 153600

// -------- scratch --------
__device__ float g_scores[N_ * K_];   // 134 MB approx scores
__device__ __half g_bimg[524288];     // [8 nc][16 ds][2 hi/lo][128 n][16 k]
__device__ float g_cnorm[K_];
__device__ float g_znorm[N_];
__device__ int   g_idx[N_];
__device__ int   g_counts[K_];
__device__ float g_part[8192];

#define MMA16816(d, a, b) \
    asm volatile("mma.sync.aligned.m16n8k16.row.col.f32.f16.f16.f32 " \
        "{%0,%1,%2,%3}, {%4,%5,%6,%7}, {%8,%9}, {%0,%1,%2,%3};" \
        : "+f"((d)[0]), "+f"((d)[1]), "+f"((d)[2]), "+f"((d)[3]) \
        : "r"((a)[0]), "r"((a)[1]), "r"((a)[2]), "r"((a)[3]), \
          "r"((b)[0]), "r"((b)[1]))

// -------- cnorm + zero counts --------
__global__ void cnorm_kernel(const float* __restrict__ cb) {
    int tid = threadIdx.x;
    int gtid = blockIdx.x * 256 + tid;
    if (gtid < K_) g_counts[gtid] = 0;
    int wid = tid >> 5, lane = tid & 31;
    int code = blockIdx.x * 8 + wid;
    float s = 0.f;
    #pragma unroll
    for (int j = 0; j < 8; j++) {
        float v = cb[(size_t)code * D_ + lane + 32 * j];
        s = fmaf(v, v, s);
    }
    #pragma unroll
    for (int o = 16; o > 0; o >>= 1) s += __shfl_down_sync(0xffffffffu, s, o);
    if (lane == 0) g_cnorm[code] = s;
}

// -------- znorm (identical arithmetic to the R2 kernel that matched reference) --------
__global__ void znorm_kernel(const float* __restrict__ z_e) {
    int r = blockIdx.x * 256 + threadIdx.x;
    int b = r >> 10, hw = r & 1023;
    const float* p = z_e + (size_t)b * (D_ * HW_) + hw;
    float s = 0.f;
    #pragma unroll 8
    for (int d = 0; d < D_; d++) {
        float v = p[(size_t)d * HW_];
        s = fmaf(v, v, s);
    }
    g_znorm[r] = s;
}

// -------- codebook -> fp16 hi/lo packed slabs --------
__global__ void prep_b_kernel(const float* __restrict__ cb) {
    int e = blockIdx.x * 256 + threadIdx.x;   // 262144
    int code = e >> 8;
    int d = e & 255;
    float v = cb[(size_t)code * D_ + d];
    __half h = __float2half(v);
    __half l = __float2half(v - __half2float(h));
    int nc = code >> 7, n = code & 127;
    int ds = d >> 4, k = d & 15;
    size_t base = ((size_t)(nc * 16 + ds) * 2) * 2048 + (size_t)n * 16 + k;
    g_bimg[base] = h;            // hi slab
    g_bimg[base + 2048] = l;     // lo slab
}

// -------- pass 1: HMMA distance GEMM (fp16 hi/lo split), scores -> g_scores --------
__global__ void __launch_bounds__(256) vq_hmma_kernel(const float* __restrict__ z_e) {
    extern __shared__ char smem[];
    __half* Ah = (__half*)(smem + SM_AHI);     // [128][260]
    __half* Al = (__half*)(smem + SM_ALO);
    __half* Bb = (__half*)(smem + SM_B);       // [2 buf][2 hi/lo][128][16]
    float*  cn = (float*)(smem + SM_CN);

    int tid = threadIdx.x;
    int w = tid >> 5, lane = tid & 31;
    int g = lane >> 2, tg = lane & 3;
    int wM = w & 3, wN = w >> 2;               // 4 M-warps x 2 N-warps
    int R0 = blockIdx.x * 128;
    int b = R0 >> 10, hw0 = R0 & 1023;
    const float* zbase = z_e + (size_t)b * (D_ * HW_) + hw0;

    #pragma unroll
    for (int i = tid; i < K_; i += 256) cn[i] = g_cnorm[i];

    for (int e = tid; e < 32768; e += 256) {
        int d = e >> 7, r = e & 127;
        float z = zbase[(size_t)d * HW_ + r];
        __half h = __float2half(z);
        __half l = __float2half(z - __half2float(h));
        Ah[r * 260 + d] = h;
        Al[r * 260 + d] = l;
    }
    __syncthreads();

    float znr[4];
    #pragma unroll
    for (int i = 0; i < 4; i++) znr[i] = g_znorm[R0 + wM * 32 + 8 * i + g];

    const int4* bimg = (const int4*)g_bimg;

    for (int n0 = 0; n0 < 8; n0++) {
        float acc[2][8][4];
        #pragma unroll
        for (int mt = 0; mt < 2; mt++)
            #pragma unroll
            for (int nt = 0; nt < 8; nt++)
                #pragma unroll
                for (int c = 0; c < 4; c++) acc[mt][nt][c] = 0.f;

        const int4* src = bimg + (size_t)(n0 * 16) * 512;
        int4 p0 = src[tid], p1 = src[tid + 256];

        for (int ds = 0; ds < 16; ds++) {
            int buf = ds & 1;
            int4* bd = (int4*)(Bb + buf * 4096);
            bd[tid] = p0; bd[tid + 256] = p1;
            __syncthreads();
            if (ds < 15) {
                const int4* s2 = bimg + (size_t)(n0 * 16 + ds + 1) * 512;
                p0 = s2[tid]; p1 = s2[tid + 256];
            }
            int k0 = ds * 16;
            const __half* Bh = Bb + buf * 4096;
            const __half* Bl = Bh + 2048;

            uint32_t ah[2][4], al[2][4], bh[8][2], bl[8][2];
            #pragma unroll
            for (int mt = 0; mt < 2; mt++) {
                const __half* pa = Ah + (wM * 32 + mt * 16 + g) * 260 + k0 + tg * 2;
                ah[mt][0] = *(const uint32_t*)pa;
                ah[mt][1] = *(const uint32_t*)(pa + 8 * 260);
                ah[mt][2] = *(const uint32_t*)(pa + 8);
                ah[mt][3] = *(const uint32_t*)(pa + 8 * 260 + 8);
            }
            #pragma unroll
            for (int nt = 0; nt < 8; nt++) {
                const __half* pb = Bh + (wN * 64 + nt * 8 + g) * 16 + tg * 2;
                bh[nt][0] = *(const uint32_t*)pb;
                bh[nt][1] = *(const uint32_t*)(pb + 8);
            }
            #pragma unroll
            for (int mt = 0; mt < 2; mt++)
                #pragma unroll
                for (int nt = 0; nt < 8; nt++) MMA16816(acc[mt][nt], ah[mt], bh[nt]);

            #pragma unroll
            for (int mt = 0; mt < 2; mt++) {
                const __half* pa = Al + (wM * 32 + mt * 16 + g) * 260 + k0 + tg * 2;
                al[mt][0] = *(const uint32_t*)pa;
                al[mt][1] = *(const uint32_t*)(pa + 8 * 260);
                al[mt][2] = *(const uint32_t*)(pa + 8);
                al[mt][3] = *(const uint32_t*)(pa + 8 * 260 + 8);
            }
            #pragma unroll
            for (int mt = 0; mt < 2; mt++)
                #pragma unroll
                for (int nt = 0; nt < 8; nt++) MMA16816(acc[mt][nt], al[mt], bh[nt]);

            #pragma unroll
            for (int nt = 0; nt < 8; nt++) {
                const __half* pb = Bl + (wN * 64 + nt * 8 + g) * 16 + tg * 2;
                bl[nt][0] = *(const uint32_t*)pb;
                bl[nt][1] = *(const uint32_t*)(pb + 8);
            }
            #pragma unroll
            for (int mt = 0; mt < 2; mt++)
                #pragma unroll
                for (int nt = 0; nt < 8; nt++) MMA16816(acc[mt][nt], ah[mt], bl[nt]);
        }

        // epilogue: scores -> g_scores (float2 per (mt,nt,half))
        #pragma unroll
        for (int nt = 0; nt < 8; nt++)
            #pragma unroll
            for (int mt = 0; mt < 2; mt++)
                #pragma unroll
                for (int h = 0; h < 2; h++) {
                    int kc = n0 * 128 + wN * 64 + nt * 8 + tg * 2;
                    int rowm = wM * 32 + mt * 16 + h * 8 + g;
                    float zn = znr[mt * 2 + h];
                    float A0 = zn + cn[kc];
                    float A1 = zn + cn[kc + 1];
                    float2 v;
                    v.x = A0 - 2.0f * acc[mt][nt][h * 2 + 0];
                    v.y = A1 - 2.0f * acc[mt][nt][h * 2 + 1];
                    *(float2*)(g_scores + (size_t)(R0 + rowm) * K_ + kc) = v;
                }
    }
}

// -------- pass 2: per-row candidate filter + exact fp32 rescoring (R2 arithmetic) --------
__global__ void __launch_bounds__(256) select_kernel(const float* __restrict__ z_e,
                                                     const float* __restrict__ cb) {
    __shared__ float zs[8][256];
    int tid = threadIdx.x, w = tid >> 5, lane = tid & 31;
    int R0 = blockIdx.x * 8;
    int b = R0 >> 10, hw0 = R0 & 1023;
    // stage z for the block's 8 rows
    for (int i = tid; i < 2048; i += 256) {
        int d = i >> 3, r = i & 7;
        zs[r][d] = z_e[(size_t)b * (D_ * HW_) + (size_t)d * HW_ + hw0 + r];
    }
    __syncthreads();

    int row = R0 + w;
    const float* srow = g_scores + (size_t)row * K_;
    float s[32];
    float vm = 3.402823466e38f;
    #pragma unroll
    for (int j = 0; j < 32; j++) {
        float v = srow[j * 32 + lane];
        s[j] = v;
        vm = fminf(vm, v);
    }
    #pragma unroll
    for (int o = 16; o > 0; o >>= 1)
        vm = fminf(vm, __shfl_xor_sync(0xffffffffu, vm, o));
    float thr = vm + CAND_T;
    float zn = g_znorm[row];

    float bv = 3.402823466e38f;
    int bk = 0x7fffffff;
    #pragma unroll
    for (int j = 0; j < 32; j++) {
        if (s[j] <= thr) {
            int k = j * 32 + lane;
            const float* cp = cb + (size_t)k * D_;
            float dot = 0.f;
            #pragma unroll 8
            for (int d = 0; d < 256; d++) dot = fmaf(zs[w][d], cp[d], dot);
            float A = zn + g_cnorm[k];
            float v = A - 2.0f * dot;
            if (v < bv || (v == bv && k < bk)) { bv = v; bk = k; }
        }
    }
    #pragma unroll
    for (int o = 16; o > 0; o >>= 1) {
        float ov = __shfl_xor_sync(0xffffffffu, bv, o);
        int   ok = __shfl_xor_sync(0xffffffffu, bk, o);
        if (ov < bv || (ov == bv && ok < bk)) { bv = ov; bk = ok; }
    }
    if (lane == 0) g_idx[row] = bk;
}

// -------- gather quantized (NCHW) + per-block SSE partials --------
__global__ void output_kernel(const float* __restrict__ z_e,
                              const float* __restrict__ cb,
                              float* __restrict__ out) {
    __shared__ float red[256];
    int tid = threadIdx.x;
    size_t e = ((size_t)blockIdx.x * 256 + tid) * 4;
    int w = (int)(e & 31);
    int h = (int)((e >> 5) & 31);
    int d = (int)((e >> 10) & 255);
    int b = (int)(e >> 18);
    int n = b * 1024 + h * 32 + w;
    float4 z = *reinterpret_cast<const float4*>(z_e + e);
    float q0 = cb[(size_t)g_idx[n + 0] * D_ + d];
    float q1 = cb[(size_t)g_idx[n + 1] * D_ + d];
    float q2 = cb[(size_t)g_idx[n + 2] * D_ + d];
    float q3 = cb[(size_t)g_idx[n + 3] * D_ + d];
    *reinterpret_cast<float4*>(out + e) = make_float4(q0, q1, q2, q3);
    float d0 = q0 - z.x, d1 = q1 - z.y, d2 = q2 - z.z, d3 = q3 - z.w;
    red[tid] = d0 * d0 + d1 * d1 + d2 * d2 + d3 * d3;
    __syncthreads();
    for (int o = 128; o > 0; o >>= 1) {
        if (tid < o) red[tid] += red[tid + o];
        __syncthreads();
    }
    if (tid == 0) g_part[blockIdx.x] = red[0];
}

// -------- zero-fill encodings --------
__global__ void zero_enc_kernel(float* __restrict__ out) {
    float2* enc = reinterpret_cast<float2*>(out + ENC_OFF);
    size_t t = (size_t)blockIdx.x * 256 + threadIdx.x;
    #pragma unroll
    for (int i = 0; i < 8; i++)
        enc[t + (size_t)i * 2097152] = make_float2(0.f, 0.f);
}

// -------- scatter one-hot + counts --------
__global__ void scatter_kernel(float* __restrict__ out) {
    int n = blockIdx.x * 256 + threadIdx.x;
    int idx = g_idx[n];
    atomicAdd(&g_counts[idx], 1);
    out[ENC_OFF + (size_t)n * K_ + idx] = 1.0f;
}

// -------- finalize: loss + perplexity --------
__global__ void finalize_kernel(float* __restrict__ out) {
    __shared__ float red[1024];
    int t = threadIdx.x;
    float s = 0.f;
    #pragma unroll
    for (int i = 0; i < 8; i++) s += g_part[t + i * 1024];
    red[t] = s;
    __syncthreads();
    for (int o = 512; o > 0; o >>= 1) {
        if (t < o) red[t] += red[t + o];
        __syncthreads();
    }
    float sse = red[0];
    __syncthreads();
    float p = (float)g_counts[t] * (1.0f / 32768.0f);
    red[t] = p * logf(p + 1e-10f);
    __syncthreads();
    for (int o = 512; o > 0; o >>= 1) {
        if (t < o) red[t] += red[t + o];
        __syncthreads();
    }
    if (t == 0) {
        float mse = sse * (1.0f / 8388608.0f);
        out[Q_ELEMS]     = 1.25f * mse;
        out[Q_ELEMS + 1] = expf(-red[0]);
    }
}

extern "C" void kernel_launch(void* const* d_in, const int* in_sizes, int n_in,
                              void* d_out, int out_size) {
    const float* z_e = (const float*)d_in[0];
    const float* cb  = (const float*)d_in[1];
    if (n_in >= 2 && in_sizes[0] < in_sizes[1]) {
        z_e = (const float*)d_in[1];
        cb  = (const float*)d_in[0];
    }
    float* out = (float*)d_out;

    cudaFuncSetAttribute(vq_hmma_kernel, cudaFuncAttributeMaxDynamicSharedMemorySize, SMEM_TOTAL);

    cnorm_kernel<<<128, 256>>>(cb);
    znorm_kernel<<<128, 256>>>(z_e);
    prep_b_kernel<<<1024, 256>>>(cb);
    vq_hmma_kernel<<<256, 256, SMEM_TOTAL>>>(z_e);
    select_kernel<<<4096, 256>>>(z_e, cb);
    output_kernel<<<8192, 256>>>(z_e, cb, out);
    zero_enc_kernel<<<8192, 256>>>(out);
    scatter_kernel<<<128, 256>>>(out);
    finalize_kernel<<<1, 1024>>>(out);
}

// round 11
// speedup vs baseline: 5.6854x; 1.4304x over previous
#include <cuda_runtime.h>
#include <cuda_fp16.h>
#include <cstdint>
#include <stdint.h>
#include <math.h>

#define B_  32
#define D_  256
#define K_  1024
#define HW_ 1024
#define N_  32768
#define Q_ELEMS 8388608
#define ENC_OFF 8388610
#define CAND_T 6.0e-4f

// SMEM layout (bytes): A_hi [128][260]h, B 2 bufs x 4096B, cnorm 4KB
#define SM_AHI   0
#define SM_B     66560
#define SM_CN    74752
#define SMEM_TOTAL 78848

// -------- scratch --------
__device__ __half g_sd[N_ * K_];      // 67 MB approx score deltas (cn - 2*dot)
__device__ __half g_bimg[262144];     // [8 nc][16 ds][128 n][16 k] hi-half slabs
__device__ float g_cnorm[K_];
__device__ float g_znorm[N_];
__device__ int   g_idx[N_];
__device__ int   g_counts[K_];
__device__ float g_part[8192];

#define MMA16816(d, a, b) \
    asm volatile("mma.sync.aligned.m16n8k16.row.col.f32.f16.f16.f32 " \
        "{%0,%1,%2,%3}, {%4,%5,%6,%7}, {%8,%9}, {%0,%1,%2,%3};" \
        : "+f"((d)[0]), "+f"((d)[1]), "+f"((d)[2]), "+f"((d)[3]) \
        : "r"((a)[0]), "r"((a)[1]), "r"((a)[2]), "r"((a)[3]), \
          "r"((b)[0]), "r"((b)[1]))

// -------- cnorm + zero counts --------
__global__ void cnorm_kernel(const float* __restrict__ cb) {
    int tid = threadIdx.x;
    int gtid = blockIdx.x * 256 + tid;
    if (gtid < K_) g_counts[gtid] = 0;
    int wid = tid >> 5, lane = tid & 31;
    int code = blockIdx.x * 8 + wid;
    float s = 0.f;
    #pragma unroll
    for (int j = 0; j < 8; j++) {
        float v = cb[(size_t)code * D_ + lane + 32 * j];
        s = fmaf(v, v, s);
    }
    #pragma unroll
    for (int o = 16; o > 0; o >>= 1) s += __shfl_down_sync(0xffffffffu, s, o);
    if (lane == 0) g_cnorm[code] = s;
}

// -------- znorm (identical arithmetic to the R2 kernel that matched reference) --------
__global__ void znorm_kernel(const float* __restrict__ z_e) {
    int r = blockIdx.x * 256 + threadIdx.x;
    int b = r >> 10, hw = r & 1023;
    const float* p = z_e + (size_t)b * (D_ * HW_) + hw;
    float s = 0.f;
    #pragma unroll 8
    for (int d = 0; d < D_; d++) {
        float v = p[(size_t)d * HW_];
        s = fmaf(v, v, s);
    }
    g_znorm[r] = s;
}

// -------- codebook -> fp16 hi packed slabs --------
__global__ void prep_b_kernel(const float* __restrict__ cb) {
    int e = blockIdx.x * 256 + threadIdx.x;   // 262144
    int code = e >> 8;
    int d = e & 255;
    float v = cb[(size_t)code * D_ + d];
    int nc = code >> 7, n = code & 127;
    int ds = d >> 4, k = d & 15;
    g_bimg[(size_t)(nc * 16 + ds) * 2048 + (size_t)n * 16 + k] = __float2half(v);
}

// -------- pass 1: single-pass HMMA distance GEMM, deltas -> g_sd (fp16) --------
__global__ void __launch_bounds__(256) vq_hmma_kernel(const float* __restrict__ z_e) {
    extern __shared__ char smem[];
    __half* Ah = (__half*)(smem + SM_AHI);     // [128][260]
    __half* Bb = (__half*)(smem + SM_B);       // [2 buf][128][16]
    float*  cn = (float*)(smem + SM_CN);

    int tid = threadIdx.x;
    int w = tid >> 5, lane = tid & 31;
    int g = lane >> 2, tg = lane & 3;
    int wM = w & 3, wN = w >> 2;               // 4 M-warps x 2 N-warps
    int R0 = blockIdx.x * 128;
    int b = R0 >> 10, hw0 = R0 & 1023;
    const float* zbase = z_e + (size_t)b * (D_ * HW_) + hw0;

    #pragma unroll
    for (int i = tid; i < K_; i += 256) cn[i] = g_cnorm[i];

    for (int e = tid; e < 32768; e += 256) {
        int d = e >> 7, r = e & 127;
        Ah[r * 260 + d] = __float2half(zbase[(size_t)d * HW_ + r]);
    }
    __syncthreads();

    const int4* bimg = (const int4*)g_bimg;

    for (int n0 = 0; n0 < 8; n0++) {
        float acc[2][8][4];
        #pragma unroll
        for (int mt = 0; mt < 2; mt++)
            #pragma unroll
            for (int nt = 0; nt < 8; nt++)
                #pragma unroll
                for (int c = 0; c < 4; c++) acc[mt][nt][c] = 0.f;

        int4 p0 = bimg[(size_t)(n0 * 16) * 256 + tid];

        for (int ds = 0; ds < 16; ds++) {
            int buf = ds & 1;
            ((int4*)(Bb + buf * 2048))[tid] = p0;
            __syncthreads();
            if (ds < 15) p0 = bimg[(size_t)(n0 * 16 + ds + 1) * 256 + tid];
            int k0 = ds * 16;
            const __half* Bh = Bb + buf * 2048;

            uint32_t ah[2][4], bh[8][2];
            #pragma unroll
            for (int mt = 0; mt < 2; mt++) {
                const __half* pa = Ah + (wM * 32 + mt * 16 + g) * 260 + k0 + tg * 2;
                ah[mt][0] = *(const uint32_t*)pa;
                ah[mt][1] = *(const uint32_t*)(pa + 8 * 260);
                ah[mt][2] = *(const uint32_t*)(pa + 8);
                ah[mt][3] = *(const uint32_t*)(pa + 8 * 260 + 8);
            }
            #pragma unroll
            for (int nt = 0; nt < 8; nt++) {
                const __half* pb = Bh + (wN * 64 + nt * 8 + g) * 16 + tg * 2;
                bh[nt][0] = *(const uint32_t*)pb;
                bh[nt][1] = *(const uint32_t*)(pb + 8);
            }
            #pragma unroll
            for (int mt = 0; mt < 2; mt++)
                #pragma unroll
                for (int nt = 0; nt < 8; nt++) MMA16816(acc[mt][nt], ah[mt], bh[nt]);
        }

        // epilogue: deltas (cn - 2*dot) -> g_sd as __half2
        #pragma unroll
        for (int nt = 0; nt < 8; nt++)
            #pragma unroll
            for (int mt = 0; mt < 2; mt++)
                #pragma unroll
                for (int h = 0; h < 2; h++) {
                    int kc = n0 * 128 + wN * 64 + nt * 8 + tg * 2;
                    int rowm = wM * 32 + mt * 16 + h * 8 + g;
                    float d0 = cn[kc]     - 2.0f * acc[mt][nt][h * 2 + 0];
                    float d1 = cn[kc + 1] - 2.0f * acc[mt][nt][h * 2 + 1];
                    *(__half2*)(g_sd + (size_t)(R0 + rowm) * K_ + kc) =
                        __floats2half2_rn(d0, d1);
                }
    }
}

// -------- pass 2: per-row candidate filter + exact fp32 rescoring (R2 arithmetic) --------
__global__ void __launch_bounds__(256) select_kernel(const float* __restrict__ z_e,
                                                     const float* __restrict__ cb) {
    __shared__ float zs[8][256];
    int tid = threadIdx.x, w = tid >> 5, lane = tid & 31;
    int R0 = blockIdx.x * 8;
    int b = R0 >> 10, hw0 = R0 & 1023;
    for (int i = tid; i < 2048; i += 256) {
        int d = i >> 3, r = i & 7;
        zs[r][d] = z_e[(size_t)b * (D_ * HW_) + (size_t)d * HW_ + hw0 + r];
    }
    __syncthreads();

    int row = R0 + w;
    const __half2* srow = (const __half2*)(g_sd + (size_t)row * K_);
    float s[32];
    float vm = 3.402823466e38f;
    #pragma unroll
    for (int j = 0; j < 16; j++) {
        float2 f = __half22float2(srow[lane * 16 + j]);
        s[2 * j] = f.x; s[2 * j + 1] = f.y;
        vm = fminf(vm, fminf(f.x, f.y));
    }
    #pragma unroll
    for (int o = 16; o > 0; o >>= 1)
        vm = fminf(vm, __shfl_xor_sync(0xffffffffu, vm, o));
    float thr = vm + CAND_T;
    float zn = g_znorm[row];

    float bv = 3.402823466e38f;
    int bk = 0x7fffffff;
    #pragma unroll
    for (int j = 0; j < 32; j++) {
        if (s[j] <= thr) {
            int k = lane * 32 + j;
            const float* cp = cb + (size_t)k * D_;
            float dot = 0.f;
            #pragma unroll 8
            for (int d = 0; d < 256; d++) dot = fmaf(zs[w][d], cp[d], dot);
            float A = zn + g_cnorm[k];
            float v = A - 2.0f * dot;
            if (v < bv || (v == bv && k < bk)) { bv = v; bk = k; }
        }
    }
    #pragma unroll
    for (int o = 16; o > 0; o >>= 1) {
        float ov = __shfl_xor_sync(0xffffffffu, bv, o);
        int   ok = __shfl_xor_sync(0xffffffffu, bk, o);
        if (ov < bv || (ov == bv && ok < bk)) { bv = ov; bk = ok; }
    }
    if (lane == 0) g_idx[row] = bk;
}

// -------- gather quantized (NCHW) + per-block SSE partials --------
__global__ void output_kernel(const float* __restrict__ z_e,
                              const float* __restrict__ cb,
                              float* __restrict__ out) {
    __shared__ float red[256];
    int tid = threadIdx.x;
    size_t e = ((size_t)blockIdx.x * 256 + tid) * 4;
    int w = (int)(e & 31);
    int h = (int)((e >> 5) & 31);
    int d = (int)((e >> 10) & 255);
    int b = (int)(e >> 18);
    int n = b * 1024 + h * 32 + w;
    float4 z = *reinterpret_cast<const float4*>(z_e + e);
    float q0 = cb[(size_t)g_idx[n + 0] * D_ + d];
    float q1 = cb[(size_t)g_idx[n + 1] * D_ + d];
    float q2 = cb[(size_t)g_idx[n + 2] * D_ + d];
    float q3 = cb[(size_t)g_idx[n + 3] * D_ + d];
    *reinterpret_cast<float4*>(out + e) = make_float4(q0, q1, q2, q3);
    float d0 = q0 - z.x, d1 = q1 - z.y, d2 = q2 - z.z, d3 = q3 - z.w;
    red[tid] = d0 * d0 + d1 * d1 + d2 * d2 + d3 * d3;
    __syncthreads();
    for (int o = 128; o > 0; o >>= 1) {
        if (tid < o) red[tid] += red[tid + o];
        __syncthreads();
    }
    if (tid == 0) g_part[blockIdx.x] = red[0];
}

// -------- fused one-hot encodings write (zero + scatter) + counts --------
__global__ void enc_kernel(float* __restrict__ out) {
    int n = blockIdx.x;
    int t = threadIdx.x;
    int idx = g_idx[n];
    if (t == 0) atomicAdd(&g_counts[idx], 1);
    float2* row = (float2*)(out + ENC_OFF + (size_t)n * K_);
    #pragma unroll
    for (int i = 0; i < 2; i++) {
        int p = t + i * 256;              // float2 index within row (512 total)
        float2 v = make_float2(0.f, 0.f);
        if ((idx >> 1) == p) { if (idx & 1) v.y = 1.f; else v.x = 1.f; }
        row[p] = v;
    }
}

// -------- finalize: loss + perplexity --------
__global__ void finalize_kernel(float* __restrict__ out) {
    __shared__ float red[1024];
    int t = threadIdx.x;
    float s = 0.f;
    #pragma unroll
    for (int i = 0; i < 8; i++) s += g_part[t + i * 1024];
    red[t] = s;
    __syncthreads();
    for (int o = 512; o > 0; o >>= 1) {
        if (t < o) red[t] += red[t + o];
        __syncthreads();
    }
    float sse = red[0];
    __syncthreads();
    float p = (float)g_counts[t] * (1.0f / 32768.0f);
    red[t] = p * logf(p + 1e-10f);
    __syncthreads();
    for (int o = 512; o > 0; o >>= 1) {
        if (t < o) red[t] += red[t + o];
        __syncthreads();
    }
    if (t == 0) {
        float mse = sse * (1.0f / 8388608.0f);
        out[Q_ELEMS]     = 1.25f * mse;
        out[Q_ELEMS + 1] = expf(-red[0]);
    }
}

extern "C" void kernel_launch(void* const* d_in, const int* in_sizes, int n_in,
                              void* d_out, int out_size) {
    const float* z_e = (const float*)d_in[0];
    const float* cb  = (const float*)d_in[1];
    if (n_in >= 2 && in_sizes[0] < in_sizes[1]) {
        z_e = (const float*)d_in[1];
        cb  = (const float*)d_in[0];
    }
    float* out = (float*)d_out;

    cudaFuncSetAttribute(vq_hmma_kernel, cudaFuncAttributeMaxDynamicSharedMemorySize, SMEM_TOTAL);

    cnorm_kernel<<<128, 256>>>(cb);
    znorm_kernel<<<128, 256>>>(z_e);
    prep_b_kernel<<<1024, 256>>>(cb);
    vq_hmma_kernel<<<256, 256, SMEM_TOTAL>>>(z_e);
    select_kernel<<<4096, 256>>>(z_e, cb);
    output_kernel<<<8192, 256>>>(z_e, cb, out);
    enc_kernel<<<32768, 256>>>(out);
    finalize_kernel<<<1, 1024>>>(out);
}

// round 12
// speedup vs baseline: 6.2468x; 1.0987x over previous
#include <cuda_runtime.h>
#include <cuda_fp16.h>
#include <cstdint>
#include <stdint.h>
#include <math.h>

#define B_  32
#define D_  256
#define K_  1024
#define HW_ 1024
#define N_  32768
#define Q_ELEMS 8388608
#define ENC_OFF 8388610
#define CAND_T 6.0e-4f

// SMEM layout (bytes): A_hi [128][260]h (66560), B 2 bufs x 8192B, cnorm 4KB
#define SM_AHI   0
#define SM_B     66560
#define SM_CN    82944
#define SMEM_TOTAL 87040

// -------- scratch --------
__device__ __half g_sd[N_ * K_];      // 67 MB approx score deltas (cn - 2*dot)
__device__ __half g_bimg[262144];     // [8 nc][16 ds][128 n][16 k] hi-half slabs
__device__ float g_cnorm[K_];
__device__ float g_znorm[N_];
__device__ float g_rowmin[N_];
__device__ int   g_idx[N_];
__device__ int   g_counts[K_];
__device__ float g_part[8192];

#define MMA16816(d, a, b) \
    asm volatile("mma.sync.aligned.m16n8k16.row.col.f32.f16.f16.f32 " \
        "{%0,%1,%2,%3}, {%4,%5,%6,%7}, {%8,%9}, {%0,%1,%2,%3};" \
        : "+f"((d)[0]), "+f"((d)[1]), "+f"((d)[2]), "+f"((d)[3]) \
        : "r"((a)[0]), "r"((a)[1]), "r"((a)[2]), "r"((a)[3]), \
          "r"((b)[0]), "r"((b)[1]))

// -------- cnorm + zero counts --------
__global__ void cnorm_kernel(const float* __restrict__ cb) {
    int tid = threadIdx.x;
    int gtid = blockIdx.x * 256 + tid;
    if (gtid < K_) g_counts[gtid] = 0;
    int wid = tid >> 5, lane = tid & 31;
    int code = blockIdx.x * 8 + wid;
    float s = 0.f;
    #pragma unroll
    for (int j = 0; j < 8; j++) {
        float v = cb[(size_t)code * D_ + lane + 32 * j];
        s = fmaf(v, v, s);
    }
    #pragma unroll
    for (int o = 16; o > 0; o >>= 1) s += __shfl_down_sync(0xffffffffu, s, o);
    if (lane == 0) g_cnorm[code] = s;
}

// -------- znorm (identical arithmetic to the R2 kernel that matched reference) --------
__global__ void znorm_kernel(const float* __restrict__ z_e) {
    int r = blockIdx.x * 256 + threadIdx.x;
    int b = r >> 10, hw = r & 1023;
    const float* p = z_e + (size_t)b * (D_ * HW_) + hw;
    float s = 0.f;
    #pragma unroll 8
    for (int d = 0; d < D_; d++) {
        float v = p[(size_t)d * HW_];
        s = fmaf(v, v, s);
    }
    g_znorm[r] = s;
}

// -------- codebook -> fp16 hi packed slabs --------
__global__ void prep_b_kernel(const float* __restrict__ cb) {
    int e = blockIdx.x * 256 + threadIdx.x;   // 262144
    int code = e >> 8;
    int d = e & 255;
    float v = cb[(size_t)code * D_ + d];
    int nc = code >> 7, n = code & 127;
    int ds = d >> 4, k = d & 15;
    g_bimg[(size_t)(nc * 16 + ds) * 2048 + (size_t)n * 16 + k] = __float2half(v);
}

// -------- pass 1: HMMA distance GEMM, deltas -> g_sd (fp16) + per-row fp32 min --------
__global__ void __launch_bounds__(256) vq_hmma_kernel(const float* __restrict__ z_e) {
    extern __shared__ char smem[];
    __half* Ah = (__half*)(smem + SM_AHI);     // [128][260]
    __half* Bb = (__half*)(smem + SM_B);       // [2 buf][2 ds][128][16]
    float*  cn = (float*)(smem + SM_CN);

    int tid = threadIdx.x;
    int w = tid >> 5, lane = tid & 31;
    int g = lane >> 2, tg = lane & 3;
    int wM = w & 3, wN = w >> 2;               // 4 M-warps x 2 N-warps
    int R0 = blockIdx.x * 128;
    int b = R0 >> 10, hw0 = R0 & 1023;
    const float* zbase = z_e + (size_t)b * (D_ * HW_) + hw0;

    #pragma unroll
    for (int i = tid; i < K_; i += 256) cn[i] = g_cnorm[i];

    for (int e = tid; e < 32768; e += 256) {
        int d = e >> 7, r = e & 127;
        Ah[r * 260 + d] = __float2half(zbase[(size_t)d * HW_ + r]);
    }
    __syncthreads();

    float vmin[4];
    #pragma unroll
    for (int i = 0; i < 4; i++) vmin[i] = 3.402823466e38f;

    const int4* bimg = (const int4*)g_bimg;

    for (int n0 = 0; n0 < 8; n0++) {
        float acc[2][8][4];
        #pragma unroll
        for (int mt = 0; mt < 2; mt++)
            #pragma unroll
            for (int nt = 0; nt < 8; nt++)
                #pragma unroll
                for (int c = 0; c < 4; c++) acc[mt][nt][c] = 0.f;

        // 8 groups of 2 ds-slabs (8KB each), double buffered with reg prefetch
        const int4* src = bimg + (size_t)(n0 * 16) * 256;
        int4 p0 = src[tid], p1 = src[tid + 256];

        for (int cg = 0; cg < 8; cg++) {
            int buf = cg & 1;
            int4* bd = (int4*)(Bb + buf * 4096);
            bd[tid] = p0; bd[tid + 256] = p1;
            __syncthreads();
            if (cg < 7) {
                const int4* s2 = bimg + (size_t)(n0 * 16 + (cg + 1) * 2) * 256;
                p0 = s2[tid]; p1 = s2[tid + 256];
            }
            #pragma unroll
            for (int dsi = 0; dsi < 2; dsi++) {
                int k0 = (cg * 2 + dsi) * 16;
                const __half* Bh = Bb + buf * 4096 + dsi * 2048;

                uint32_t ah[2][4], bh[8][2];
                #pragma unroll
                for (int mt = 0; mt < 2; mt++) {
                    const __half* pa = Ah + (wM * 32 + mt * 16 + g) * 260 + k0 + tg * 2;
                    ah[mt][0] = *(const uint32_t*)pa;
                    ah[mt][1] = *(const uint32_t*)(pa + 8 * 260);
                    ah[mt][2] = *(const uint32_t*)(pa + 8);
                    ah[mt][3] = *(const uint32_t*)(pa + 8 * 260 + 8);
                }
                #pragma unroll
                for (int nt = 0; nt < 8; nt++) {
                    const __half* pb = Bh + (wN * 64 + nt * 8 + g) * 16 + tg * 2;
                    bh[nt][0] = *(const uint32_t*)pb;
                    bh[nt][1] = *(const uint32_t*)(pb + 8);
                }
                #pragma unroll
                for (int mt = 0; mt < 2; mt++)
                    #pragma unroll
                    for (int nt = 0; nt < 8; nt++) MMA16816(acc[mt][nt], ah[mt], bh[nt]);
            }
        }

        // epilogue: deltas (cn - 2*dot) -> g_sd as __half2; track fp32 row min
        #pragma unroll
        for (int nt = 0; nt < 8; nt++)
            #pragma unroll
            for (int mt = 0; mt < 2; mt++)
                #pragma unroll
                for (int h = 0; h < 2; h++) {
                    int kc = n0 * 128 + wN * 64 + nt * 8 + tg * 2;
                    int rowm = wM * 32 + mt * 16 + h * 8 + g;
                    float d0 = cn[kc]     - 2.0f * acc[mt][nt][h * 2 + 0];
                    float d1 = cn[kc + 1] - 2.0f * acc[mt][nt][h * 2 + 1];
                    vmin[mt * 2 + h] = fminf(vmin[mt * 2 + h], fminf(d0, d1));
                    *(__half2*)(g_sd + (size_t)(R0 + rowm) * K_ + kc) =
                        __floats2half2_rn(d0, d1);
                }
    }

    // reduce row minima: over tg lanes, then over the two wN halves via smem
    __syncthreads();
    float* sv = (float*)(Bb);    // 2 x 128 floats
    #pragma unroll
    for (int i = 0; i < 4; i++) {
        float v = vmin[i];
        v = fminf(v, __shfl_xor_sync(0xffffffffu, v, 1));
        v = fminf(v, __shfl_xor_sync(0xffffffffu, v, 2));
        if (tg == 0) {
            int mt = i >> 1, h = i & 1;
            sv[wN * 128 + wM * 32 + mt * 16 + h * 8 + g] = v;
        }
    }
    __syncthreads();
    if (tid < 128)
        g_rowmin[R0 + tid] = fminf(sv[tid], sv[128 + tid]);
}

// -------- pass 2: candidate filter (coalesced) + exact fp32 rescoring (R2 arithmetic) --------
__global__ void __launch_bounds__(256) select_kernel(const float* __restrict__ z_e,
                                                     const float* __restrict__ cb) {
    __shared__ float zs[8][256];
    int tid = threadIdx.x, w = tid >> 5, lane = tid & 31;
    int R0 = blockIdx.x * 8;
    int b = R0 >> 10, hw0 = R0 & 1023;
    for (int i = tid; i < 2048; i += 256) {
        int d = i >> 3, r = i & 7;
        zs[r][d] = z_e[(size_t)b * (D_ * HW_) + (size_t)d * HW_ + hw0 + r];
    }
    __syncthreads();

    int row = R0 + w;
    const __half2* sr = (const __half2*)(g_sd + (size_t)row * K_);
    float thr = g_rowmin[row] + CAND_T;
    float zn = g_znorm[row];

    float bv = 3.402823466e38f;
    int bk = 0x7fffffff;
    #pragma unroll
    for (int j = 0; j < 16; j++) {
        float2 f = __half22float2(sr[j * 32 + lane]);   // coalesced
        int kb = (j * 32 + lane) * 2;
        #pragma unroll
        for (int hh = 0; hh < 2; hh++) {
            float sc = hh ? f.y : f.x;
            if (sc <= thr) {
                int k = kb + hh;
                const float* cp = cb + (size_t)k * D_;
                float dot = 0.f;
                #pragma unroll 8
                for (int d = 0; d < 256; d++) dot = fmaf(zs[w][d], cp[d], dot);
                float A = zn + g_cnorm[k];
                float v = A - 2.0f * dot;
                if (v < bv || (v == bv && k < bk)) { bv = v; bk = k; }
            }
        }
    }
    #pragma unroll
    for (int o = 16; o > 0; o >>= 1) {
        float ov = __shfl_xor_sync(0xffffffffu, bv, o);
        int   ok = __shfl_xor_sync(0xffffffffu, bk, o);
        if (ov < bv || (ov == bv && ok < bk)) { bv = ov; bk = ok; }
    }
    if (lane == 0) g_idx[row] = bk;
}

// -------- gather quantized (NCHW) + per-block SSE partials --------
__global__ void output_kernel(const float* __restrict__ z_e,
                              const float* __restrict__ cb,
                              float* __restrict__ out) {
    __shared__ float red[256];
    int tid = threadIdx.x;
    size_t e = ((size_t)blockIdx.x * 256 + tid) * 4;
    int w = (int)(e & 31);
    int h = (int)((e >> 5) & 31);
    int d = (int)((e >> 10) & 255);
    int b = (int)(e >> 18);
    int n = b * 1024 + h * 32 + w;
    float4 z = *reinterpret_cast<const float4*>(z_e + e);
    float q0 = cb[(size_t)g_idx[n + 0] * D_ + d];
    float q1 = cb[(size_t)g_idx[n + 1] * D_ + d];
    float q2 = cb[(size_t)g_idx[n + 2] * D_ + d];
    float q3 = cb[(size_t)g_idx[n + 3] * D_ + d];
    *reinterpret_cast<float4*>(out + e) = make_float4(q0, q1, q2, q3);
    float d0 = q0 - z.x, d1 = q1 - z.y, d2 = q2 - z.z, d3 = q3 - z.w;
    red[tid] = d0 * d0 + d1 * d1 + d2 * d2 + d3 * d3;
    __syncthreads();
    for (int o = 128; o > 0; o >>= 1) {
        if (tid < o) red[tid] += red[tid + o];
        __syncthreads();
    }
    if (tid == 0) g_part[blockIdx.x] = red[0];
}

// -------- fused one-hot encodings write (zero + scatter) + counts --------
__global__ void enc_kernel(float* __restrict__ out) {
    int n = blockIdx.x;
    int t = threadIdx.x;
    int idx = g_idx[n];
    if (t == 0) atomicAdd(&g_counts[idx], 1);
    float2* row = (float2*)(out + ENC_OFF + (size_t)n * K_);
    #pragma unroll
    for (int i = 0; i < 2; i++) {
        int p = t + i * 256;              // float2 index within row (512 total)
        float2 v = make_float2(0.f, 0.f);
        if ((idx >> 1) == p) { if (idx & 1) v.y = 1.f; else v.x = 1.f; }
        row[p] = v;
    }
}

// -------- finalize: loss + perplexity --------
__global__ void finalize_kernel(float* __restrict__ out) {
    __shared__ float red[1024];
    int t = threadIdx.x;
    float s = 0.f;
    #pragma unroll
    for (int i = 0; i < 8; i++) s += g_part[t + i * 1024];
    red[t] = s;
    __syncthreads();
    for (int o = 512; o > 0; o >>= 1) {
        if (t < o) red[t] += red[t + o];
        __syncthreads();
    }
    float sse = red[0];
    __syncthreads();
    float p = (float)g_counts[t] * (1.0f / 32768.0f);
    red[t] = p * logf(p + 1e-10f);
    __syncthreads();
    for (int o = 512; o > 0; o >>= 1) {
        if (t < o) red[t] += red[t + o];
        __syncthreads();
    }
    if (t == 0) {
        float mse = sse * (1.0f / 8388608.0f);
        out[Q_ELEMS]     = 1.25f * mse;
        out[Q_ELEMS + 1] = expf(-red[0]);
    }
}

extern "C" void kernel_launch(void* const* d_in, const int* in_sizes, int n_in,
                              void* d_out, int out_size) {
    const float* z_e = (const float*)d_in[0];
    const float* cb  = (const float*)d_in[1];
    if (n_in >= 2 && in_sizes[0] < in_sizes[1]) {
        z_e = (const float*)d_in[1];
        cb  = (const float*)d_in[0];
    }
    float* out = (float*)d_out;

    cudaFuncSetAttribute(vq_hmma_kernel, cudaFuncAttributeMaxDynamicSharedMemorySize, SMEM_TOTAL);

    cnorm_kernel<<<128, 256>>>(cb);
    znorm_kernel<<<128, 256>>>(z_e);
    prep_b_kernel<<<1024, 256>>>(cb);
    vq_hmma_kernel<<<256, 256, SMEM_TOTAL>>>(z_e);
    select_kernel<<<4096, 256>>>(z_e, cb);
    output_kernel<<<8192, 256>>>(z_e, cb, out);
    enc_kernel<<<32768, 256>>>(out);
    finalize_kernel<<<1, 1024>>>(out);
}

// round 14
// speedup vs baseline: 6.4646x; 1.0349x over previous
#include <cuda_runtime.h>
#include <cuda_fp16.h>
#include <cstdint>
#include <stdint.h>
#include <math.h>

#define B_  32
#define D_  256
#define K_  1024
#define HW_ 1024
#define N_  32768
#define Q_ELEMS 8388608
#define ENC_OFF 8388610
#define CAND_T 6.0e-4f

// SMEM layout (bytes): A_hi [128][260]h (66560), B 2 bufs x 16384B, cnorm 4KB
#define SM_AHI   0
#define SM_B     66560
#define SM_CN    99328
#define SMEM_TOTAL 103424

// -------- scratch --------
__device__ __half g_sd[N_ * K_];      // 67 MB approx score deltas (cn - 2*dot)
__device__ __half g_bimg[262144];     // [8 nc][16 ds][128 n][16 k] hi-half slabs
__device__ float g_cnorm[K_];
__device__ float g_znorm[N_];
__device__ float g_rowmin[N_];
__device__ int   g_idx[N_];
__device__ int   g_counts[K_];
__device__ float g_part[8192];

#define MMA16816(d, a, b) \
    asm volatile("mma.sync.aligned.m16n8k16.row.col.f32.f16.f16.f32 " \
        "{%0,%1,%2,%3}, {%4,%5,%6,%7}, {%8,%9}, {%0,%1,%2,%3};" \
        : "+f"((d)[0]), "+f"((d)[1]), "+f"((d)[2]), "+f"((d)[3]) \
        : "r"((a)[0]), "r"((a)[1]), "r"((a)[2]), "r"((a)[3]), \
          "r"((b)[0]), "r"((b)[1]))

static __device__ __forceinline__ uint32_t smem_u32(const void* p) {
    uint32_t a;
    asm("{ .reg .u64 t; cvta.to.shared.u64 t, %1; cvt.u32.u64 %0, t; }" : "=r"(a) : "l"(p));
    return a;
}
static __device__ __forceinline__ void cp_async16(uint32_t dst, const void* src) {
    asm volatile("cp.async.cg.shared.global [%0], [%1], 16;" :: "r"(dst), "l"(src) : "memory");
}
#define CP_COMMIT() asm volatile("cp.async.commit_group;" ::: "memory")
#define CP_WAIT1()  asm volatile("cp.async.wait_group 1;" ::: "memory")
#define CP_WAIT0()  asm volatile("cp.async.wait_group 0;" ::: "memory")

// -------- cnorm + zero counts --------
__global__ void cnorm_kernel(const float* __restrict__ cb) {
    int tid = threadIdx.x;
    int gtid = blockIdx.x * 256 + tid;
    if (gtid < K_) g_counts[gtid] = 0;
    int wid = tid >> 5, lane = tid & 31;
    int code = blockIdx.x * 8 + wid;
    float s = 0.f;
    #pragma unroll
    for (int j = 0; j < 8; j++) {
        float v = cb[(size_t)code * D_ + lane + 32 * j];
        s = fmaf(v, v, s);
    }
    #pragma unroll
    for (int o = 16; o > 0; o >>= 1) s += __shfl_down_sync(0xffffffffu, s, o);
    if (lane == 0) g_cnorm[code] = s;
}

// -------- znorm (identical arithmetic to the R2 kernel that matched reference) --------
__global__ void znorm_kernel(const float* __restrict__ z_e) {
    int r = blockIdx.x * 256 + threadIdx.x;
    int b = r >> 10, hw = r & 1023;
    const float* p = z_e + (size_t)b * (D_ * HW_) + hw;
    float s = 0.f;
    #pragma unroll 8
    for (int d = 0; d < D_; d++) {
        float v = p[(size_t)d * HW_];
        s = fmaf(v, v, s);
    }
    g_znorm[r] = s;
}

// -------- codebook -> fp16 hi packed slabs --------
__global__ void prep_b_kernel(const float* __restrict__ cb) {
    int e = blockIdx.x * 256 + threadIdx.x;   // 262144
    int code = e >> 8;
    int d = e & 255;
    float v = cb[(size_t)code * D_ + d];
    int nc = code >> 7, n = code & 127;
    int ds = d >> 4, k = d & 15;
    g_bimg[(size_t)(nc * 16 + ds) * 2048 + (size_t)n * 16 + k] = __float2half(v);
}

// -------- pass 1: HMMA GEMM w/ cp.async B pipeline; deltas->g_sd + fp32 row min --------
__global__ void __launch_bounds__(256) vq_hmma_kernel(const float* __restrict__ z_e) {
    extern __shared__ char smem[];
    __half* Ah = (__half*)(smem + SM_AHI);     // [128][260]
    float*  cn = (float*)(smem + SM_CN);
    uint32_t sbB = smem_u32(smem) + SM_B;

    int tid = threadIdx.x;
    int w = tid >> 5, lane = tid & 31;
    int g = lane >> 2, tg = lane & 3;
    int wM = w & 3, wN = w >> 2;               // 4 M-warps x 2 N-warps
    int R0 = blockIdx.x * 128;
    int b = R0 >> 10, hw0 = R0 & 1023;
    const float* zbase = z_e + (size_t)b * (D_ * HW_) + hw0;

    #pragma unroll
    for (int i = tid; i < K_; i += 256) cn[i] = g_cnorm[i];

    for (int e = tid; e < 32768; e += 256) {
        int d = e >> 7, r = e & 127;
        Ah[r * 260 + d] = __float2half(zbase[(size_t)d * HW_ + r]);
    }

    // issue cg0 B loads (16KB: 64B per thread) while A conversion settles
    {
        const char* src = (const char*)g_bimg + (size_t)tid * 64;
        uint32_t dst = sbB + tid * 64;
        #pragma unroll
        for (int i = 0; i < 4; i++) cp_async16(dst + i * 16, src + i * 16);
        CP_COMMIT();
    }
    __syncthreads();

    float vmin[4];
    #pragma unroll
    for (int i = 0; i < 4; i++) vmin[i] = 3.402823466e38f;

    float acc[2][8][4];
    #pragma unroll
    for (int mt = 0; mt < 2; mt++)
        #pragma unroll
        for (int nt = 0; nt < 8; nt++)
            #pragma unroll
            for (int c = 0; c < 4; c++) acc[mt][nt][c] = 0.f;

    for (int cg = 0; cg < 32; cg++) {           // cg = n0*4 + dsgroup, 16KB each
        if (cg < 31) {
            const char* src = (const char*)g_bimg + (size_t)(cg + 1) * 16384 + (size_t)tid * 64;
            uint32_t dst = sbB + ((cg + 1) & 1) * 16384 + tid * 64;
            #pragma unroll
            for (int i = 0; i < 4; i++) cp_async16(dst + i * 16, src + i * 16);
            CP_COMMIT();
            CP_WAIT1();
        } else {
            CP_WAIT0();
        }
        __syncthreads();

        const __half* Bbuf = (const __half*)(smem + SM_B + (cg & 1) * 16384);
        int k0b = (cg & 3) * 64;                // d-offset of this cg within n0

        #pragma unroll
        for (int dsi = 0; dsi < 4; dsi++) {
            int k0 = k0b + dsi * 16;
            const __half* Bh = Bbuf + dsi * 2048;

            uint32_t ah[2][4], bh[8][2];
            #pragma unroll
            for (int mt = 0; mt < 2; mt++) {
                const __half* pa = Ah + (wM * 32 + mt * 16 + g) * 260 + k0 + tg * 2;
                ah[mt][0] = *(const uint32_t*)pa;
                ah[mt][1] = *(const uint32_t*)(pa + 8 * 260);
                ah[mt][2] = *(const uint32_t*)(pa + 8);
                ah[mt][3] = *(const uint32_t*)(pa + 8 * 260 + 8);
            }
            #pragma unroll
            for (int nt = 0; nt < 8; nt++) {
                const __half* pb = Bh + (wN * 64 + nt * 8 + g) * 16 + tg * 2;
                bh[nt][0] = *(const uint32_t*)pb;
                bh[nt][1] = *(const uint32_t*)(pb + 8);
            }
            #pragma unroll
            for (int mt = 0; mt < 2; mt++)
                #pragma unroll
                for (int nt = 0; nt < 8; nt++) MMA16816(acc[mt][nt], ah[mt], bh[nt]);
        }
        __syncthreads();

        if ((cg & 3) == 3) {
            int n0 = cg >> 2;
            // epilogue: deltas -> g_sd (half2); track fp32 row min; reset acc
            #pragma unroll
            for (int nt = 0; nt < 8; nt++)
                #pragma unroll
                for (int mt = 0; mt < 2; mt++)
                    #pragma unroll
                    for (int h = 0; h < 2; h++) {
                        int kc = n0 * 128 + wN * 64 + nt * 8 + tg * 2;
                        int rowm = wM * 32 + mt * 16 + h * 8 + g;
                        float d0 = cn[kc]     - 2.0f * acc[mt][nt][h * 2 + 0];
                        float d1 = cn[kc + 1] - 2.0f * acc[mt][nt][h * 2 + 1];
                        vmin[mt * 2 + h] = fminf(vmin[mt * 2 + h], fminf(d0, d1));
                        *(__half2*)(g_sd + (size_t)(R0 + rowm) * K_ + kc) =
                            __floats2half2_rn(d0, d1);
                        acc[mt][nt][h * 2 + 0] = 0.f;
                        acc[mt][nt][h * 2 + 1] = 0.f;
                    }
        }
    }

    // reduce row minima: tg lanes, then the two wN halves via smem
    __syncthreads();
    float* sv = (float*)(smem + SM_B);
    #pragma unroll
    for (int i = 0; i < 4; i++) {
        float v = vmin[i];
        v = fminf(v, __shfl_xor_sync(0xffffffffu, v, 1));
        v = fminf(v, __shfl_xor_sync(0xffffffffu, v, 2));
        if (tg == 0) {
            int mt = i >> 1, h = i & 1;
            sv[wN * 128 + wM * 32 + mt * 16 + h * 8 + g] = v;
        }
    }
    __syncthreads();
    if (tid < 128)
        g_rowmin[R0 + tid] = fminf(sv[tid], sv[128 + tid]);
}

// -------- pass 2: filter + exact fp32 rescore (R2 arithmetic) + fused one-hot --------
__global__ void __launch_bounds__(256) select_kernel(const float* __restrict__ z_e,
                                                     const float* __restrict__ cb,
                                                     float* __restrict__ out) {
    __shared__ float zs[8][256];
    int tid = threadIdx.x, w = tid >> 5, lane = tid & 31;
    int R0 = blockIdx.x * 8;
    int b = R0 >> 10, hw0 = R0 & 1023;
    for (int i = tid; i < 2048; i += 256) {
        int d = i >> 3, r = i & 7;
        zs[r][d] = z_e[(size_t)b * (D_ * HW_) + (size_t)d * HW_ + hw0 + r];
    }
    __syncthreads();

    int row = R0 + w;
    const __half2* sr = (const __half2*)(g_sd + (size_t)row * K_);
    float thr = g_rowmin[row] + CAND_T;
    float zn = g_znorm[row];

    float bv = 3.402823466e38f;
    int bk = 0x7fffffff;
    #pragma unroll
    for (int j = 0; j < 16; j++) {
        float2 f = __half22float2(sr[j * 32 + lane]);   // coalesced
        int kb = (j * 32 + lane) * 2;
        #pragma unroll
        for (int hh = 0; hh < 2; hh++) {
            float sc = hh ? f.y : f.x;
            if (sc <= thr) {
                int k = kb + hh;
                const float* cp = cb + (size_t)k * D_;
                float dot = 0.f;
                #pragma unroll 8
                for (int d = 0; d < 256; d++) dot = fmaf(zs[w][d], cp[d], dot);
                float A = zn + g_cnorm[k];
                float v = A - 2.0f * dot;
                if (v < bv || (v == bv && k < bk)) { bv = v; bk = k; }
            }
        }
    }
    #pragma unroll
    for (int o = 16; o > 0; o >>= 1) {
        float ov = __shfl_xor_sync(0xffffffffu, bv, o);
        int   ok = __shfl_xor_sync(0xffffffffu, bk, o);
        if (ov < bv || (ov == bv && ok < bk)) { bv = ov; bk = ok; }
    }
    int kwin = __shfl_sync(0xffffffffu, bk, 0);
    if (lane == 0) {
        g_idx[row] = kwin;
        atomicAdd(&g_counts[kwin], 1);
    }
    // fused one-hot row write (interleaved, coalesced float2)
    float2* rowp = (float2*)(out + ENC_OFF + (size_t)row * K_);
    int target = kwin >> 1;
    #pragma unroll
    for (int i = 0; i < 16; i++) {
        int p = i * 32 + lane;
        float2 v = make_float2(0.f, 0.f);
        if (p == target) { if (kwin & 1) v.y = 1.f; else v.x = 1.f; }
        rowp[p] = v;
    }
}

// -------- gather quantized (NCHW) + per-block SSE partials --------
__global__ void output_kernel(const float* __restrict__ z_e,
                              const float* __restrict__ cb,
                              float* __restrict__ out) {
    __shared__ float red[8];
    int tid = threadIdx.x, wid = tid >> 5, lane = tid & 31;
    size_t e = ((size_t)blockIdx.x * 256 + tid) * 4;
    int w = (int)(e & 31);
    int h = (int)((e >> 5) & 31);
    int d = (int)((e >> 10) & 255);
    int b = (int)(e >> 18);
    int n = b * 1024 + h * 32 + w;
    float4 z = *reinterpret_cast<const float4*>(z_e + e);
    float q0 = cb[(size_t)g_idx[n + 0] * D_ + d];
    float q1 = cb[(size_t)g_idx[n + 1] * D_ + d];
    float q2 = cb[(size_t)g_idx[n + 2] * D_ + d];
    float q3 = cb[(size_t)g_idx[n + 3] * D_ + d];
    *reinterpret_cast<float4*>(out + e) = make_float4(q0, q1, q2, q3);
    float d0 = q0 - z.x, d1 = q1 - z.y, d2 = q2 - z.z, d3 = q3 - z.w;
    float v = d0 * d0 + d1 * d1 + d2 * d2 + d3 * d3;
    #pragma unroll
    for (int o = 16; o > 0; o >>= 1) v += __shfl_down_sync(0xffffffffu, v, o);
    if (lane == 0) red[wid] = v;
    __syncthreads();
    if (tid == 0) {
        float s = 0.f;
        #pragma unroll
        for (int i = 0; i < 8; i++) s += red[i];
        g_part[blockIdx.x] = s;
    }
}

// -------- finalize: loss + perplexity --------
__global__ void finalize_kernel(float* __restrict__ out) {
    __shared__ float red[1024];
    int t = threadIdx.x;
    float s = 0.f;
    #pragma unroll
    for (int i = 0; i < 8; i++) s += g_part[t + i * 1024];
    red[t] = s;
    __syncthreads();
    for (int o = 512; o > 0; o >>= 1) {
        if (t < o) red[t] += red[t + o];
        __syncthreads();
    }
    float sse = red[0];
    __syncthreads();
    float p = (float)g_counts[t] * (1.0f / 32768.0f);
    red[t] = p * logf(p + 1e-10f);
    __syncthreads();
    for (int o = 512; o > 0; o >>= 1) {
        if (t < o) red[t] += red[t + o];
        __syncthreads();
    }
    if (t == 0) {
        float mse = sse * (1.0f / 8388608.0f);
        out[Q_ELEMS]     = 1.25f * mse;
        out[Q_ELEMS + 1] = expf(-red[0]);
    }
}

extern "C" void kernel_launch(void* const* d_in, const int* in_sizes, int n_in,
                              void* d_out, int out_size) {
    const float* z_e = (const float*)d_in[0];
    const float* cb  = (const float*)d_in[1];
    if (n_in >= 2 && in_sizes[0] < in_sizes[1]) {
        z_e = (const float*)d_in[1];
        cb  = (const float*)d_in[0];
    }
    float* out = (float*)d_out;

    cudaFuncSetAttribute(vq_hmma_kernel, cudaFuncAttributeMaxDynamicSharedMemorySize, SMEM_TOTAL);

    cnorm_kernel<<<128, 256>>>(cb);
    znorm_kernel<<<128, 256>>>(z_e);
    prep_b_kernel<<<1024, 256>>>(cb);
    vq_hmma_kernel<<<256, 256, SMEM_TOTAL>>>(z_e);
    select_kernel<<<4096, 256>>>(z_e, cb, out);
    output_kernel<<<8192, 256>>>(z_e, cb, out);
    finalize_kernel<<<1, 1024>>>(out);
}